// round 13
// baseline (speedup 1.0000x reference)
#include <cuda_runtime.h>
#include <math.h>

// Problem dims (fixed by setup_inputs)
#define BB   8
#define HH   512
#define WW   512
#define HP   128
#define WP   128
#define CF   256
#define SP   (HP*WP)            // 16384 spatial per plane
#define NF   (BB*CF*SP)         // 33554432 F_in elements
#define NV4  (NF/4)             // 8388608 float4s
#define BPSM 5                  // 40 warps/SM: +25% outstanding loads vs 4
#define GRID (148*BPSM)         // 740: all blocks simultaneously resident
#define TPB  256
#define NTHREADS (GRID*TPB)     // 189440
// Phase-3: 32768 atoms (1 channel x 1024 px), exact contiguous split
#define TOT_ATOMS 32768

// Device scratch (no allocations allowed). Partial slots overwritten every
// replay; g_bar is monotonic -> replay-safe.
__device__ double g_ps[GRID];
__device__ double g_pq[GRID];
__device__ float  g_img_ds[BB*3*SP];   // 4x4 avg-pooled img (1.5 MiB)
__device__ float  g_dh[BB*SP];         // distance-valued D_h
__device__ float4 g_wpack[2*CF];       // [2c]={gw0,gw1,gw2,gb}, [2c+1]={bw..}
__device__ unsigned int g_bar;         // monotonic ticket barrier

// ---------------------------------------------------------------- grid barrier
// Monotonic: correct across unlimited graph replays. Deadlock-free because
// all GRID blocks are simultaneously resident (740 = 148 SMs x 5 via bounds).
__device__ __forceinline__ void grid_barrier() {
    __syncthreads();
    if (threadIdx.x == 0) {
        __threadfence();
        unsigned int old = atomicAdd(&g_bar, 1u);
        unsigned int target = old - (old % GRID) + GRID;
        while (*((volatile unsigned int*)&g_bar) < target) __nanosleep(64);
        __threadfence();
    }
    __syncthreads();
}

// ---------------------------------------------------------------- on-the-fly 4x4 max-pool of raw mask
__device__ __forceinline__ float pooled_max(const float* __restrict__ mb, int h, int w) {
    const float* p = mb + (size_t)(h * 4) * WW + w * 4;
    float mx = 0.f;
    #pragma unroll
    for (int r = 0; r < 4; r++) {
        float4 v = __ldg((const float4*)(p + (size_t)r * WW));
        mx = fmaxf(mx, fmaxf(fmaxf(v.x, v.y), fmaxf(v.z, v.w)));
    }
    return mx;
}

// ---------------------------------------------------------------- the whole problem, one kernel
__global__ void __launch_bounds__(TPB, BPSM)
fused_kernel(const float4* __restrict__ F,
             const float*  __restrict__ img,
             const float*  __restrict__ mask,
             const float*  __restrict__ gw, const float* __restrict__ gB,
             const float*  __restrict__ bw, const float* __restrict__ bB,
             float4* __restrict__ out) {
    __shared__ double s_s[TPB];
    __shared__ double s_q[TPB];
    __shared__ float  s_stats[2];
    const int tid = threadIdx.x;
    const int bid = blockIdx.x;
    const int gt  = bid * TPB + tid;        // 0..189439

    // ---------------- Phase 1a: weight packing (first 256 global threads)
    if (gt < CF) {
        g_wpack[2*gt]     = make_float4(gw[3*gt], gw[3*gt+1], gw[3*gt+2], gB[gt]);
        g_wpack[2*gt + 1] = make_float4(bw[3*gt], bw[3*gt+1], bw[3*gt+2], bB[gt]);
    }

    // ---------------- Phase 1b: img 4x4 avg-pool (<=3 outputs per thread)
    // BEFORE the F sweep so these reads don't evict F from L2.
    for (int idx = gt; idx < BB * 3 * SP; idx += NTHREADS) {
        int wp = idx & 127;
        int hp = (idx >> 7) & 127;
        int ch = (idx >> 14) % 3;
        int b  = idx / (3 * SP);
        const float* p = img + ((size_t)(b * 3 + ch) * HH + hp * 4) * WW + wp * 4;
        float s = 0.f;
        #pragma unroll
        for (int r = 0; r < 4; r++) {
            float4 v = __ldcs((const float4*)(p + (size_t)r * WW));
            s += (v.x + v.y) + (v.z + v.w);
        }
        g_img_ds[idx] = s * (1.f / 16.f);
    }

    // ---------------- Phase 1c: Chebyshev DT straight from the raw mask
    // 5 iters of (3x3 dilate -> 2^-i on newly reached) == per pooled pixel:
    //   d = Cheb dist to nearest pooled-1; value = (d<=5) ? 2^-d : 0
    if (gt < BB * SP) {
        int b   = gt >> 14;
        int rem = gt & 16383;
        int h = rem >> 7, w = rem & 127;
        const float* mb = mask + (size_t)b * 3 * HH * WW;   // channel 0
        float val;
        if (pooled_max(mb, h, w) > 0.5f) {
            val = 1.f;                                       // dominant path
        } else {
            val = 0.f;
            for (int d = 1; d <= 5; d++) {
                bool hit = false;
                int y0 = h - d, y1 = h + d;
                int xlo = w - d < 0 ? 0 : w - d;
                int xhi = w + d > WP - 1 ? WP - 1 : w + d;
                if (y0 >= 0) for (int x = xlo; x <= xhi; x++) hit |= pooled_max(mb, y0, x) > 0.5f;
                if (y1 < HP) for (int x = xlo; x <= xhi; x++) hit |= pooled_max(mb, y1, x) > 0.5f;
                int ylo = h - d + 1 < 0 ? 0 : h - d + 1;
                int yhi = h + d - 1 > HP - 1 ? HP - 1 : h + d - 1;
                if (w - d >= 0) for (int y = ylo; y <= yhi; y++) hit |= pooled_max(mb, y, w - d) > 0.5f;
                if (w + d < WP) for (int y = ylo; y <= yhi; y++) hit |= pooled_max(mb, y, w + d) > 0.5f;
                if (hit) { val = exp2f(-(float)d); break; }
            }
        }
        g_dh[gt] = val;
    }

    // ---------------- Phase 1d: F sum/sumsq, blocked-contiguous sweep.
    // Each block streams a contiguous ~181KB region front-to-back. At the
    // end, L2 (~126MB) holds the last ~85% of every region (~uniform
    // residency for phase 3's reverse walk).
    {
        const long rstart = ((long)bid * NV4) / GRID;
        const long rend   = ((long)(bid + 1) * NV4) / GRID;
        float ps = 0.f, pq = 0.f;
        long i = rstart + tid;
        #pragma unroll 11
        for (; i < rend; i += TPB) {
            float4 v = __ldcg(&F[i]);
            ps += (v.x + v.y) + (v.z + v.w);
            pq += (v.x * v.x + v.y * v.y) + (v.z * v.z + v.w * v.w);
        }
        s_s[tid] = (double)ps;
        s_q[tid] = (double)pq;
        __syncthreads();
        for (int off = 128; off > 0; off >>= 1) {
            if (tid < off) { s_s[tid] += s_s[tid + off]; s_q[tid] += s_q[tid + off]; }
            __syncthreads();
        }
        if (tid == 0) { g_ps[bid] = s_s[0]; g_pq[bid] = s_q[0]; }
    }

    // ================ the one grid-wide barrier ================
    grid_barrier();

    // ---------------- Phase 2: every block folds the partials into stats
    {
        double ls = 0.0, lq = 0.0;
        for (int i = tid; i < GRID; i += TPB) { ls += g_ps[i]; lq += g_pq[i]; }
        s_s[tid] = ls; s_q[tid] = lq;
        __syncthreads();
        for (int off = 128; off > 0; off >>= 1) {
            if (tid < off) { s_s[tid] += s_s[tid + off]; s_q[tid] += s_q[tid + off]; }
            __syncthreads();
        }
        if (tid == 0) {
            double n = (double)NF;
            double mean = s_s[0] / n;
            double var = (s_q[0] - s_s[0] * s_s[0] / n) / (n - 1.0);
            double scale = 1.0 / sqrt(var * var + 1e-5);
            s_stats[0] = (float)(mean * scale);
            s_stats[1] = (float)scale;
        }
        __syncthreads();
    }

    const float ms = s_stats[0];
    const float sc = s_stats[1];

    // ---------------- Phase 3: fused epilogue over 32768 atoms.
    // Atom a = g*256 + ch, g = b*16 + chunk (1 channel x 1024 px each).
    // Block takes the EXACT contiguous range [bid*TOT/GRID,(bid+1)*TOT/GRID)
    // -> 44 or 45 atoms (2% straggle). Range spans <=2 (b,chunk) groups, so
    // coefficient maps load at most twice per block. DESCENDING order:
    // highest F address first = freshest in L2.
    {
        const int start = (int)(((long)bid * TOT_ATOMS) / GRID);
        const int end   = (int)(((long)(bid + 1) * TOT_ATOMS) / GRID);
        const int glo = start >> 8;
        const int ghi = (end - 1) >> 8;

        for (int g = ghi; g >= glo; g--) {
            const int b     = g >> 4;
            const int chunk = g & 15;
            const int pix   = chunk * 1024 + tid * 4;

            const int sb = b * SP + pix;
            const int ib = b * 3 * SP + pix;

            float4 dh = *(const float4*)&g_dh[sb];
            float4 p0 = *(const float4*)&g_img_ds[ib];
            float4 p1 = *(const float4*)&g_img_ds[ib + SP];
            float4 p2 = *(const float4*)&g_img_ds[ib + 2 * SP];

            float q0[4] = { p0.x * dh.x, p0.y * dh.y, p0.z * dh.z, p0.w * dh.w };
            float q1[4] = { p1.x * dh.x, p1.y * dh.y, p1.z * dh.z, p1.w * dh.w };
            float q2[4] = { p2.x * dh.x, p2.y * dh.y, p2.z * dh.z, p2.w * dh.w };
            float q3[4] = { dh.x, dh.y, dh.z, dh.w };

            const int alo = (g << 8)       > start ? (g << 8)       : start;
            const int ahi = ((g + 1) << 8) < end   ? ((g + 1) << 8) : end;
            const size_t base4 = (size_t)(b * CF) * 4096 + (pix >> 2);

            #pragma unroll 4
            for (int a = ahi - 1; a >= alo; a--) {
                const int ch = a & 255;
                float4 gwv = __ldg(&g_wpack[2 * ch]);
                float4 bwv = __ldg(&g_wpack[2 * ch + 1]);
                float4 f = __ldcs(&F[base4 + (size_t)ch * 4096]);
                float4 o;
                float gc, bc, fn;

                gc = fmaf(gwv.x, q0[0], fmaf(gwv.y, q1[0], fmaf(gwv.z, q2[0], gwv.w * q3[0])));
                bc = fmaf(bwv.x, q0[0], fmaf(bwv.y, q1[0], fmaf(bwv.z, q2[0], bwv.w * q3[0])));
                fn = fmaf(f.x, sc, -ms);
                o.x = fmaf(fn, gc, bc);

                gc = fmaf(gwv.x, q0[1], fmaf(gwv.y, q1[1], fmaf(gwv.z, q2[1], gwv.w * q3[1])));
                bc = fmaf(bwv.x, q0[1], fmaf(bwv.y, q1[1], fmaf(bwv.z, q2[1], bwv.w * q3[1])));
                fn = fmaf(f.y, sc, -ms);
                o.y = fmaf(fn, gc, bc);

                gc = fmaf(gwv.x, q0[2], fmaf(gwv.y, q1[2], fmaf(gwv.z, q2[2], gwv.w * q3[2])));
                bc = fmaf(bwv.x, q0[2], fmaf(bwv.y, q1[2], fmaf(bwv.z, q2[2], bwv.w * q3[2])));
                fn = fmaf(f.z, sc, -ms);
                o.z = fmaf(fn, gc, bc);

                gc = fmaf(gwv.x, q0[3], fmaf(gwv.y, q1[3], fmaf(gwv.z, q2[3], gwv.w * q3[3])));
                bc = fmaf(bwv.x, q0[3], fmaf(bwv.y, q1[3], fmaf(bwv.z, q2[3], bwv.w * q3[3])));
                fn = fmaf(f.w, sc, -ms);
                o.w = fmaf(fn, gc, bc);

                __stcs(&out[base4 + (size_t)ch * 4096], o);
            }
        }
    }
}

// ---------------------------------------------------------------- launch
extern "C" void kernel_launch(void* const* d_in, const int* in_sizes, int n_in,
                              void* d_out, int out_size) {
    const float* F_in    = (const float*)d_in[0];
    const float* img_p   = (const float*)d_in[1];
    const float* mask    = (const float*)d_in[2];
    const float* gamma_w = (const float*)d_in[3];
    const float* gamma_b = (const float*)d_in[4];
    const float* beta_w  = (const float*)d_in[5];
    const float* beta_b  = (const float*)d_in[6];
    // d_in[7] = n_ds (==2), d_in[8] = n (==2): fixed by problem shapes.
    float* out = (float*)d_out;

    fused_kernel<<<GRID, TPB>>>((const float4*)F_in, img_p, mask,
                                gamma_w, gamma_b, beta_w, beta_b,
                                (float4*)out);
}

// round 14
// speedup vs baseline: 1.0960x; 1.0960x over previous
#include <cuda_runtime.h>
#include <math.h>
#include <cstdint>

// Problem dims (fixed by setup_inputs)
#define BB   8
#define HH   512
#define WW   512
#define HP   128
#define WP   128
#define CF   256
#define SP   (HP*WP)            // 16384 spatial per plane
#define NF   (BB*CF*SP)         // 33554432 F_in elements
#define NV4  (NF/4)             // 8388608 float4s
#define GRID 592                // 148 SMs x 4 blocks: all resident
#define TPB  256
#define NTHREADS (GRID*TPB)
// Phase-1: 8192 chunks of 16KB (1024 float4) cover F exactly
#define NCHUNK 8192
// Phase-3: 16384 pair-atoms (2 channels x 1024 px = 8KB each)
#define PA_TOT 16384

// Device scratch (no allocations). Slots overwritten every replay; g_bar is
// monotonic -> replay-safe. smem mbarriers re-initialized every launch.
__device__ double g_ps[GRID];
__device__ double g_pq[GRID];
__device__ float  g_img_ds[BB*3*SP];   // 4x4 avg-pooled img (1.5 MiB)
__device__ float  g_dh[BB*SP];         // distance-valued D_h
__device__ float4 g_wpack[2*CF];       // [2c]={gw0..,gb}, [2c+1]={bw..,bb}
__device__ unsigned int g_bar;         // monotonic ticket barrier

// ---------------------------------------------------------------- PTX helpers
__device__ __forceinline__ unsigned smem_u32(const void* p) {
    return (unsigned)__cvta_generic_to_shared(p);
}
__device__ __forceinline__ void mbar_init(unsigned mbar, unsigned count) {
    asm volatile("mbarrier.init.shared.b64 [%0], %1;" :: "r"(mbar), "r"(count) : "memory");
}
__device__ __forceinline__ void mbar_expect_tx(unsigned mbar, unsigned bytes) {
    asm volatile("mbarrier.arrive.expect_tx.shared.b64 _, [%0], %1;"
                 :: "r"(mbar), "r"(bytes) : "memory");
}
__device__ __forceinline__ void bulk_g2s(unsigned dst, const void* src,
                                         unsigned bytes, unsigned mbar) {
    asm volatile("cp.async.bulk.shared::cluster.global.mbarrier::complete_tx::bytes "
                 "[%0], [%1], %2, [%3];"
                 :: "r"(dst), "l"(src), "r"(bytes), "r"(mbar) : "memory");
}
__device__ __forceinline__ void mbar_wait(unsigned mbar, unsigned parity) {
    asm volatile(
        "{\n\t"
        ".reg .pred P1;\n\t"
        "WL_%=:\n\t"
        "mbarrier.try_wait.parity.acquire.cta.shared::cta.b64 P1, [%0], %1, 0x989680;\n\t"
        "@P1 bra WD_%=;\n\t"
        "bra.uni WL_%=;\n\t"
        "WD_%=:\n\t"
        "}"
        :: "r"(mbar), "r"(parity) : "memory");
}

// ---------------------------------------------------------------- grid barrier
__device__ __forceinline__ void grid_barrier() {
    __syncthreads();
    if (threadIdx.x == 0) {
        __threadfence();
        unsigned int old = atomicAdd(&g_bar, 1u);
        unsigned int target = old - (old % GRID) + GRID;
        while (*((volatile unsigned int*)&g_bar) < target) __nanosleep(64);
        __threadfence();
    }
    __syncthreads();
}

// ---------------------------------------------------------------- on-the-fly 4x4 max-pool of raw mask
__device__ __forceinline__ float pooled_max(const float* __restrict__ mb, int h, int w) {
    const float* p = mb + (size_t)(h * 4) * WW + w * 4;
    float mx = 0.f;
    #pragma unroll
    for (int r = 0; r < 4; r++) {
        float4 v = __ldg((const float4*)(p + (size_t)r * WW));
        mx = fmaxf(mx, fmaxf(fmaxf(v.x, v.y), fmaxf(v.z, v.w)));
    }
    return mx;
}

// ---------------------------------------------------------------- the whole problem, one kernel
__global__ void __launch_bounds__(TPB, 4)
fused_kernel(const float* __restrict__ Ff,
             const float* __restrict__ img,
             const float* __restrict__ mask,
             const float* __restrict__ gw, const float* __restrict__ gB,
             const float* __restrict__ bw, const float* __restrict__ bB,
             float4* __restrict__ out) {
    // smem: 32KB TMA buffer (phase1: 2x16KB stages; phase3: 4x8KB stages),
    // 8 mbarriers (phase1 uses 0..1, phase3 uses 2..5 -> clean parity),
    // reduction arrays.
    __shared__ __align__(128) char s_buf[32768];
    __shared__ __align__(8) unsigned long long s_mb[8];
    __shared__ double s_s[TPB];
    __shared__ double s_q[TPB];
    __shared__ float  s_stats[2];
    const int tid = threadIdx.x;
    const int bid = blockIdx.x;
    const int gt  = bid * TPB + tid;
    const unsigned buf0 = smem_u32(s_buf);

    if (tid == 0) {
        #pragma unroll
        for (int i = 0; i < 8; i++) mbar_init(smem_u32(&s_mb[i]), 1);
    }
    __syncthreads();

    // ---------------- Phase 1a: weight packing (first 256 global threads)
    if (gt < CF) {
        g_wpack[2*gt]     = make_float4(gw[3*gt], gw[3*gt+1], gw[3*gt+2], gB[gt]);
        g_wpack[2*gt + 1] = make_float4(bw[3*gt], bw[3*gt+1], bw[3*gt+2], bB[gt]);
    }

    // ---------------- Phase 1b: img 4x4 avg-pool
    for (int idx = gt; idx < BB * 3 * SP; idx += NTHREADS) {
        int wp = idx & 127;
        int hp = (idx >> 7) & 127;
        int ch = (idx >> 14) % 3;
        int b  = idx / (3 * SP);
        const float* p = img + ((size_t)(b * 3 + ch) * HH + hp * 4) * WW + wp * 4;
        float s = 0.f;
        #pragma unroll
        for (int r = 0; r < 4; r++) {
            float4 v = __ldcs((const float4*)(p + (size_t)r * WW));
            s += (v.x + v.y) + (v.z + v.w);
        }
        g_img_ds[idx] = s * (1.f / 16.f);
    }

    // ---------------- Phase 1c: Chebyshev DT from the raw mask
    // (5 dilate iters == d = Cheb dist to nearest pooled-1; val = 2^-d, d<=5)
    if (gt < BB * SP) {
        int b   = gt >> 14;
        int rem = gt & 16383;
        int h = rem >> 7, w = rem & 127;
        const float* mb = mask + (size_t)b * 3 * HH * WW;   // channel 0
        float val;
        if (pooled_max(mb, h, w) > 0.5f) {
            val = 1.f;                                       // dominant path
        } else {
            val = 0.f;
            for (int d = 1; d <= 5; d++) {
                bool hit = false;
                int y0 = h - d, y1 = h + d;
                int xlo = w - d < 0 ? 0 : w - d;
                int xhi = w + d > WP - 1 ? WP - 1 : w + d;
                if (y0 >= 0) for (int x = xlo; x <= xhi; x++) hit |= pooled_max(mb, y0, x) > 0.5f;
                if (y1 < HP) for (int x = xlo; x <= xhi; x++) hit |= pooled_max(mb, y1, x) > 0.5f;
                int ylo = h - d + 1 < 0 ? 0 : h - d + 1;
                int yhi = h + d - 1 > HP - 1 ? HP - 1 : h + d - 1;
                if (w - d >= 0) for (int y = ylo; y <= yhi; y++) hit |= pooled_max(mb, y, w - d) > 0.5f;
                if (w + d < WP) for (int y = ylo; y <= yhi; y++) hit |= pooled_max(mb, y, w + d) > 0.5f;
                if (hit) { val = exp2f(-(float)d); break; }
            }
        }
        g_dh[gt] = val;
    }

    // ---------------- Phase 1d: F sum/sumsq via TMA double-buffer.
    // Block streams its contiguous chunk range [cs, ce) of 16KB chunks; each
    // stage keeps 16KB in flight -> concurrency no longer warp-limited.
    {
        const int cs = (int)(((long)bid * NCHUNK) / GRID);
        const int ce = (int)(((long)(bid + 1) * NCHUNK) / GRID);
        const int nch = ce - cs;

        if (tid == 0) {
            #pragma unroll
            for (int j = 0; j < 2; j++) {
                if (j < nch) {
                    unsigned mb = smem_u32(&s_mb[j]);
                    mbar_expect_tx(mb, 16384u);
                    bulk_g2s(buf0 + j * 16384u, Ff + (size_t)(cs + j) * 4096, 16384u, mb);
                }
            }
        }

        float ps = 0.f, pq = 0.f;
        for (int k = 0; k < nch; k++) {
            const int st = k & 1;
            mbar_wait(smem_u32(&s_mb[st]), (k >> 1) & 1);
            const float4* sb = (const float4*)(s_buf + st * 16384);
            #pragma unroll
            for (int r = 0; r < 4; r++) {
                float4 v = sb[tid + r * TPB];
                ps += (v.x + v.y) + (v.z + v.w);
                pq += (v.x * v.x + v.y * v.y) + (v.z * v.z + v.w * v.w);
            }
            __syncthreads();
            if (tid == 0 && k + 2 < nch) {
                unsigned mb = smem_u32(&s_mb[st]);
                mbar_expect_tx(mb, 16384u);
                bulk_g2s(buf0 + st * 16384u, Ff + (size_t)(cs + k + 2) * 4096, 16384u, mb);
            }
        }
        s_s[tid] = (double)ps;
        s_q[tid] = (double)pq;
        __syncthreads();
        for (int off = 128; off > 0; off >>= 1) {
            if (tid < off) { s_s[tid] += s_s[tid + off]; s_q[tid] += s_q[tid + off]; }
            __syncthreads();
        }
        if (tid == 0) { g_ps[bid] = s_s[0]; g_pq[bid] = s_q[0]; }
    }

    // ================ the one grid-wide barrier ================
    grid_barrier();

    // ---------------- Phase 2: fold partials into stats
    {
        double ls = 0.0, lq = 0.0;
        for (int i = tid; i < GRID; i += TPB) { ls += g_ps[i]; lq += g_pq[i]; }
        s_s[tid] = ls; s_q[tid] = lq;
        __syncthreads();
        for (int off = 128; off > 0; off >>= 1) {
            if (tid < off) { s_s[tid] += s_s[tid + off]; s_q[tid] += s_q[tid + off]; }
            __syncthreads();
        }
        if (tid == 0) {
            double n = (double)NF;
            double mean = s_s[0] / n;
            double var = (s_q[0] - s_s[0] * s_s[0] / n) / (n - 1.0);
            double scale = 1.0 / sqrt(var * var + 1e-5);
            s_stats[0] = (float)(mean * scale);
            s_stats[1] = (float)scale;
        }
        __syncthreads();
    }

    const float ms = s_stats[0];
    const float sc = s_stats[1];

    // ---------------- Phase 3: fused epilogue via 4-stage TMA pipeline.
    // Pair-atom a: g = a>>7 (b*16+chunk), cp = a&127 -> channels 2cp, 2cp+1;
    // two 4KB copies per atom (one mbarrier, expect_tx 8192). Exact
    // contiguous split over blocks; processed in DESCENDING address order
    // (freshest-in-L2 first). Stages use mbar[2..5] (fresh parity).
    {
        const int start = (int)(((long)bid * PA_TOT) / GRID);
        const int end   = (int)(((long)(bid + 1) * PA_TOT) / GRID);
        const int n = end - start;

        // issue j-th (local) atom into stage j&3
        auto issue = [&](int j) {
            const int a  = end - 1 - j;
            const int g  = a >> 7;
            const int cp = a & 127;
            const int b  = g >> 4;
            const int chunk = g & 15;
            const float* src = Ff + ((size_t)(b * CF + cp * 2) * SP + chunk * 1024);
            const int st = j & 3;
            unsigned mb = smem_u32(&s_mb[2 + st]);
            unsigned dst = buf0 + (unsigned)st * 8192u;
            mbar_expect_tx(mb, 8192u);
            bulk_g2s(dst,         src,      4096u, mb);
            bulk_g2s(dst + 4096u, src + SP, 4096u, mb);
        };

        if (tid == 0) {
            for (int j = 0; j < (n < 4 ? n : 4); j++) issue(j);
        }

        int cur_g = -1;
        float q0[4], q1[4], q2[4], q3[4];
        size_t obase = 0;
        int pix = 0;

        for (int j = 0; j < n; j++) {
            const int a  = end - 1 - j;
            const int g  = a >> 7;
            const int cp = a & 127;
            const int b  = g >> 4;
            const int chunk = g & 15;

            if (g != cur_g) {
                cur_g = g;
                pix = chunk * 1024 + tid * 4;
                const int sb = b * SP + pix;
                const int ib = b * 3 * SP + pix;
                float4 dh = *(const float4*)&g_dh[sb];
                float4 p0 = *(const float4*)&g_img_ds[ib];
                float4 p1 = *(const float4*)&g_img_ds[ib + SP];
                float4 p2 = *(const float4*)&g_img_ds[ib + 2 * SP];
                q0[0]=p0.x*dh.x; q0[1]=p0.y*dh.y; q0[2]=p0.z*dh.z; q0[3]=p0.w*dh.w;
                q1[0]=p1.x*dh.x; q1[1]=p1.y*dh.y; q1[2]=p1.z*dh.z; q1[3]=p1.w*dh.w;
                q2[0]=p2.x*dh.x; q2[1]=p2.y*dh.y; q2[2]=p2.z*dh.z; q2[3]=p2.w*dh.w;
                q3[0]=dh.x; q3[1]=dh.y; q3[2]=dh.z; q3[3]=dh.w;
                obase = (size_t)(b * CF) * 4096 + (pix >> 2);
            }

            const int st = j & 3;
            mbar_wait(smem_u32(&s_mb[2 + st]), (j >> 2) & 1);

            const float4* sb4 = (const float4*)(s_buf + st * 8192);
            #pragma unroll
            for (int h = 0; h < 2; h++) {
                const int ch = cp * 2 + h;
                float4 gwv = __ldg(&g_wpack[2 * ch]);
                float4 bwv = __ldg(&g_wpack[2 * ch + 1]);
                float4 f = sb4[h * 256 + tid];
                float4 o;
                float gc, bc, fn;

                gc = fmaf(gwv.x, q0[0], fmaf(gwv.y, q1[0], fmaf(gwv.z, q2[0], gwv.w * q3[0])));
                bc = fmaf(bwv.x, q0[0], fmaf(bwv.y, q1[0], fmaf(bwv.z, q2[0], bwv.w * q3[0])));
                fn = fmaf(f.x, sc, -ms);
                o.x = fmaf(fn, gc, bc);

                gc = fmaf(gwv.x, q0[1], fmaf(gwv.y, q1[1], fmaf(gwv.z, q2[1], gwv.w * q3[1])));
                bc = fmaf(bwv.x, q0[1], fmaf(bwv.y, q1[1], fmaf(bwv.z, q2[1], bwv.w * q3[1])));
                fn = fmaf(f.y, sc, -ms);
                o.y = fmaf(fn, gc, bc);

                gc = fmaf(gwv.x, q0[2], fmaf(gwv.y, q1[2], fmaf(gwv.z, q2[2], gwv.w * q3[2])));
                bc = fmaf(bwv.x, q0[2], fmaf(bwv.y, q1[2], fmaf(bwv.z, q2[2], bwv.w * q3[2])));
                fn = fmaf(f.z, sc, -ms);
                o.z = fmaf(fn, gc, bc);

                gc = fmaf(gwv.x, q0[3], fmaf(gwv.y, q1[3], fmaf(gwv.z, q2[3], gwv.w * q3[3])));
                bc = fmaf(bwv.x, q0[3], fmaf(bwv.y, q1[3], fmaf(bwv.z, q2[3], bwv.w * q3[3])));
                fn = fmaf(f.w, sc, -ms);
                o.w = fmaf(fn, gc, bc);

                __stcs(&out[obase + (size_t)ch * 4096], o);
            }
            __syncthreads();
            if (tid == 0 && j + 4 < n) issue(j + 4);
        }
    }
}

// ---------------------------------------------------------------- launch
extern "C" void kernel_launch(void* const* d_in, const int* in_sizes, int n_in,
                              void* d_out, int out_size) {
    const float* F_in    = (const float*)d_in[0];
    const float* img_p   = (const float*)d_in[1];
    const float* mask    = (const float*)d_in[2];
    const float* gamma_w = (const float*)d_in[3];
    const float* gamma_b = (const float*)d_in[4];
    const float* beta_w  = (const float*)d_in[5];
    const float* beta_b  = (const float*)d_in[6];
    // d_in[7] = n_ds (==2), d_in[8] = n (==2): fixed by problem shapes.
    float* out = (float*)d_out;

    fused_kernel<<<GRID, TPB>>>(F_in, img_p, mask,
                                gamma_w, gamma_b, beta_w, beta_b,
                                (float4*)out);
}